// round 1
// baseline (speedup 1.0000x reference)
#include <cuda_runtime.h>

#define D 16
#define NMAX 100000

// Scratch (static __device__ — no allocation allowed)
__device__ float4 g_fs[NMAX * 4];     // feat_src  [N,16]
__device__ float4 g_fd[NMAX * 4];     // feat_dst  [N,16]
__device__ float4 g_num[NMAX * 4];    // sum ex * fs[src] per dst node
__device__ float  g_den[NMAX];        // sum ex per dst node
__device__ float4 g_h2[NMAX * 4];     // layer-1 output / layer-2 input

// ---------------------------------------------------------------------------
// feat kernel: fs = h@Wsrc + bsrc ; fd = h@Wdst + bdst ; zero accumulators
// ---------------------------------------------------------------------------
__global__ void feat_kernel(const float* __restrict__ h, int use_h2,
                            const float* __restrict__ Wsrc, const float* __restrict__ bsrc,
                            const float* __restrict__ Wdst, const float* __restrict__ bdst,
                            int N) {
    __shared__ float sWs[D * D], sWd[D * D], sbs[D], sbd[D];
    int tid = threadIdx.x;
    if (tid < D * D) { sWs[tid] = Wsrc[tid]; sWd[tid] = Wdst[tid]; }
    if (tid < D)     { sbs[tid] = bsrc[tid]; sbd[tid] = bdst[tid]; }
    __syncthreads();

    int n = blockIdx.x * blockDim.x + tid;
    if (n >= N) return;

    const float4* h4 = use_h2 ? (g_h2 + n * 4) : ((const float4*)h + n * 4);
    float hr[D];
#pragma unroll
    for (int i = 0; i < 4; i++) {
        float4 v = h4[i];
        hr[4 * i + 0] = v.x; hr[4 * i + 1] = v.y; hr[4 * i + 2] = v.z; hr[4 * i + 3] = v.w;
    }
    float os[D], od[D];
#pragma unroll
    for (int j = 0; j < D; j++) { os[j] = sbs[j]; od[j] = sbd[j]; }
#pragma unroll
    for (int k = 0; k < D; k++) {
        float hv = hr[k];
#pragma unroll
        for (int j = 0; j < D; j++) {
            os[j] = fmaf(hv, sWs[k * D + j], os[j]);
            od[j] = fmaf(hv, sWd[k * D + j], od[j]);
        }
    }
#pragma unroll
    for (int i = 0; i < 4; i++) {
        g_fs[n * 4 + i]  = make_float4(os[4 * i], os[4 * i + 1], os[4 * i + 2], os[4 * i + 3]);
        g_fd[n * 4 + i]  = make_float4(od[4 * i], od[4 * i + 1], od[4 * i + 2], od[4 * i + 3]);
        g_num[n * 4 + i] = make_float4(0.f, 0.f, 0.f, 0.f);
    }
    g_den[n] = 0.f;
}

// ---------------------------------------------------------------------------
// edge kernel: score = sum_j lr02(fs[s][j]+fd[t][j]) * attn[j]
//              ex = exp(score)   (softmax shift-invariance: no max needed,
//              scores are O(8) for this data, no overflow risk in fp32)
//              denom[t] += ex ; num[t][:] += ex * fs[s][:]
// ---------------------------------------------------------------------------
__device__ __forceinline__ void red_add_v4(float4* addr, float x, float y, float z, float w) {
    asm volatile("red.global.add.v4.f32 [%0], {%1, %2, %3, %4};"
                 :: "l"(addr), "f"(x), "f"(y), "f"(z), "f"(w) : "memory");
}

__device__ __forceinline__ float lr02(float x) {
    return x > 0.f ? x : 0.2f * x;
}

__global__ void edge_kernel(const int* __restrict__ src, const int* __restrict__ dst,
                            const float* __restrict__ attn, int E) {
    __shared__ float sat[D];
    if (threadIdx.x < D) sat[threadIdx.x] = attn[threadIdx.x];
    __syncthreads();

    int e = blockIdx.x * blockDim.x + threadIdx.x;
    if (e >= E) return;

    int s = src[e];
    int t = dst[e];

    float4 a0 = g_fs[s * 4 + 0], a1 = g_fs[s * 4 + 1], a2 = g_fs[s * 4 + 2], a3 = g_fs[s * 4 + 3];
    float4 b0 = g_fd[t * 4 + 0], b1 = g_fd[t * 4 + 1], b2 = g_fd[t * 4 + 2], b3 = g_fd[t * 4 + 3];

    float score = 0.f;
    score = fmaf(lr02(a0.x + b0.x), sat[0],  score);
    score = fmaf(lr02(a0.y + b0.y), sat[1],  score);
    score = fmaf(lr02(a0.z + b0.z), sat[2],  score);
    score = fmaf(lr02(a0.w + b0.w), sat[3],  score);
    score = fmaf(lr02(a1.x + b1.x), sat[4],  score);
    score = fmaf(lr02(a1.y + b1.y), sat[5],  score);
    score = fmaf(lr02(a1.z + b1.z), sat[6],  score);
    score = fmaf(lr02(a1.w + b1.w), sat[7],  score);
    score = fmaf(lr02(a2.x + b2.x), sat[8],  score);
    score = fmaf(lr02(a2.y + b2.y), sat[9],  score);
    score = fmaf(lr02(a2.z + b2.z), sat[10], score);
    score = fmaf(lr02(a2.w + b2.w), sat[11], score);
    score = fmaf(lr02(a3.x + b3.x), sat[12], score);
    score = fmaf(lr02(a3.y + b3.y), sat[13], score);
    score = fmaf(lr02(a3.z + b3.z), sat[14], score);
    score = fmaf(lr02(a3.w + b3.w), sat[15], score);

    float ex = __expf(score);

    atomicAdd(&g_den[t], ex);   // result unused -> compiles to REDG
    red_add_v4(&g_num[t * 4 + 0], ex * a0.x, ex * a0.y, ex * a0.z, ex * a0.w);
    red_add_v4(&g_num[t * 4 + 1], ex * a1.x, ex * a1.y, ex * a1.z, ex * a1.w);
    red_add_v4(&g_num[t * 4 + 2], ex * a2.x, ex * a2.y, ex * a2.z, ex * a2.w);
    red_add_v4(&g_num[t * 4 + 3], ex * a3.x, ex * a3.y, ex * a3.z, ex * a3.w);
}

// ---------------------------------------------------------------------------
// node kernel: out = leaky_relu(num/denom, 0.01); empty nodes -> 0
// ---------------------------------------------------------------------------
__device__ __forceinline__ float lr001(float x) {
    return x > 0.f ? x : 0.01f * x;
}

__global__ void node_kernel(float* __restrict__ out, int to_internal, int N) {
    int n = blockIdx.x * blockDim.x + threadIdx.x;
    if (n >= N) return;
    float den = g_den[n];
    float inv = (den > 0.f) ? (1.0f / den) : 0.f;
    float4* o = to_internal ? (g_h2 + n * 4) : ((float4*)out + n * 4);
#pragma unroll
    for (int i = 0; i < 4; i++) {
        float4 v = g_num[n * 4 + i];
        float4 r;
        r.x = lr001(v.x * inv);
        r.y = lr001(v.y * inv);
        r.z = lr001(v.z * inv);
        r.w = lr001(v.w * inv);
        o[i] = r;
    }
}

// ---------------------------------------------------------------------------
// launch
// ---------------------------------------------------------------------------
extern "C" void kernel_launch(void* const* d_in, const int* in_sizes, int n_in,
                              void* d_out, int out_size) {
    const float* emb  = (const float*)d_in[0];
    const int*   src1 = (const int*)d_in[1];
    const int*   dst1 = (const int*)d_in[2];
    const int*   src2 = (const int*)d_in[3];
    const int*   dst2 = (const int*)d_in[4];
    const float* Ws1  = (const float*)d_in[5];
    const float* bs1  = (const float*)d_in[6];
    const float* Wd1  = (const float*)d_in[7];
    const float* bd1  = (const float*)d_in[8];
    const float* at1  = (const float*)d_in[9];
    const float* Ws2  = (const float*)d_in[10];
    const float* bs2  = (const float*)d_in[11];
    const float* Wd2  = (const float*)d_in[12];
    const float* bd2  = (const float*)d_in[13];
    const float* at2  = (const float*)d_in[14];

    int N  = in_sizes[0] / D;
    int E1 = in_sizes[1];
    int E2 = in_sizes[3];

    int nbN = (N + 255) / 256;

    // Layer 1
    feat_kernel<<<nbN, 256>>>(emb, 0, Ws1, bs1, Wd1, bd1, N);
    edge_kernel<<<(E1 + 255) / 256, 256>>>(src1, dst1, at1, E1);
    node_kernel<<<nbN, 256>>>(nullptr, 1, N);

    // Layer 2
    feat_kernel<<<nbN, 256>>>(nullptr, 1, Ws2, bs2, Wd2, bd2, N);
    edge_kernel<<<(E2 + 255) / 256, 256>>>(src2, dst2, at2, E2);
    node_kernel<<<nbN, 256>>>((float*)d_out, 0, N);
}